// round 14
// baseline (speedup 1.0000x reference)
#include <cuda_runtime.h>
#include <cuda_fp16.h>
#include <cstdint>

#define ROWS 8192
#define KDIM 128
#define NPER 82          // int(8192 * 1 / 100) + 1
#define EPS  1.25e-3f    // certified |dot_hh - dot| bound coeff (x ||a||*||b||)

// Scratch (device globals: no allocation allowed)
__device__ float  g_r[ROWS];            // dot(x1_i, x2_i) / ||x2_i||
__device__ float  g_n1[ROWS];           // ||x1_i||
__device__ float  g_n2[ROWS];           // ||x2_j||
__device__ int    g_cb[ROWS];           // packed (cert<<16 | bord)
__device__ int    g_cnt[ROWS];          // final per-row count (or 0 / NPER marker)
__device__ int    g_flag[ROWS];         // flagged row list
__device__ int    g_nflag;              // number of flagged rows
__device__ __half g_x1h[ROWS * KDIM];   // fp16 rn of inputs
__device__ __half g_x2h[ROWS * KDIM];

__device__ __forceinline__ uint32_t smem_u32(const void* p) {
    uint32_t a;
    asm("{ .reg .u64 t; cvta.to.shared.u64 t, %1; cvt.u32.u64 %0, t; }"
        : "=r"(a) : "l"(p));
    return a;
}

#define LDSM_X4(r0, r1, r2, r3, addr) \
    asm volatile("ldmatrix.sync.aligned.m8n8.x4.shared.b16 {%0,%1,%2,%3}, [%4];" \
                 : "=r"(r0), "=r"(r1), "=r"(r2), "=r"(r3) : "r"(addr))

#define MMA_16816(c, a, b0, b1) \
    asm volatile("mma.sync.aligned.m16n8k16.row.col.f32.f16.f16.f32 " \
                 "{%0,%1,%2,%3}, {%4,%5,%6,%7}, {%8,%9}, {%0,%1,%2,%3};" \
                 : "+f"((c)[0]), "+f"((c)[1]), "+f"((c)[2]), "+f"((c)[3]) \
                 : "r"((a)[0]), "r"((a)[1]), "r"((a)[2]), "r"((a)[3]), \
                   "r"(b0), "r"(b1))

#define CP_ASYNC16(dst, src) \
    asm volatile("cp.async.cg.shared.global [%0], [%1], 16;" :: "r"(dst), "l"(src))
#define CP_COMMIT() asm volatile("cp.async.commit_group;" ::: "memory")

// ---------------------------------------------------------------------------
// Kernel A: thresholds + zero counters + fp16 conversion of both inputs.
// ---------------------------------------------------------------------------
__global__ void prep_kernel(const float* __restrict__ x1,
                            const float* __restrict__ x2) {
    int warp = (blockIdx.x * blockDim.x + threadIdx.x) >> 5;
    int lane = threadIdx.x & 31;
    if (warp >= ROWS) return;
    float4 a = *(const float4*)(x1 + warp * KDIM + lane * 4);
    float4 b = *(const float4*)(x2 + warp * KDIM + lane * 4);

    int base = warp * KDIM + lane * 4;
    {
        __half h0 = __float2half_rn(a.x), h1 = __float2half_rn(a.y);
        __half h2 = __float2half_rn(a.z), h3 = __float2half_rn(a.w);
        half2 H0 = __halves2half2(h0, h1), H1 = __halves2half2(h2, h3);
        *(uint2*)(g_x1h + base) = make_uint2(*(unsigned*)&H0, *(unsigned*)&H1);
    }
    {
        __half h0 = __float2half_rn(b.x), h1 = __float2half_rn(b.y);
        __half h2 = __float2half_rn(b.z), h3 = __float2half_rn(b.w);
        half2 H0 = __halves2half2(h0, h1), H1 = __halves2half2(h2, h3);
        *(uint2*)(g_x2h + base) = make_uint2(*(unsigned*)&H0, *(unsigned*)&H1);
    }

    float s1 = a.x * a.x + a.y * a.y + a.z * a.z + a.w * a.w;
    float s2 = b.x * b.x + b.y * b.y + b.z * b.z + b.w * b.w;
    float d  = a.x * b.x + a.y * b.y + a.z * b.z + a.w * b.w;
    #pragma unroll
    for (int o = 16; o > 0; o >>= 1) {
        s1 += __shfl_down_sync(0xffffffffu, s1, o);
        s2 += __shfl_down_sync(0xffffffffu, s2, o);
        d  += __shfl_down_sync(0xffffffffu, d,  o);
    }
    if (lane == 0) {
        float n2 = sqrtf(s2);
        g_n1[warp] = sqrtf(s1);
        g_n2[warp] = n2;
        g_r[warp]  = d / n2;
        g_cb[warp] = 0;
        if (warp == 0) g_nflag = 0;
    }
}

// ---------------------------------------------------------------------------
// Kernel B: hh-only counting GEMM, per row packed (cert<<16 | bord).
// Tile BM=128 x BN=128, 256 threads (8 warps, 2x4), warp tile 64x32.
// K=128 fully resident: 4 buffers of 16 KB (A_hi 8K + B_hi 8K), all cp.async
// issued up front, progressive wait_group — no WAR syncs. 64 KB smem,
// 2 CTAs/SM so load/epilogue of one CTA overlaps compute of the other.
// ---------------------------------------------------------------------------
#define CH 16384       // bytes per chunk buffer

__device__ __forceinline__ void load_chunk(uint32_t bufb, int i0, int j0,
                                           int kc, int tid) {
    const int s  = tid & 3;
    const int rh = tid >> 2;           // 0..63
    const int swsh  = ((s ^ ((rh >> 1) & 3)) << 4);
    const int r2    = rh + 64;
    const int swsh2 = ((s ^ ((r2 >> 1) & 3)) << 4);
    CP_ASYNC16(bufb +        rh * 64 + swsh,  g_x1h + (i0 + rh) * KDIM + kc + s * 8);
    CP_ASYNC16(bufb +        r2 * 64 + swsh2, g_x1h + (i0 + r2) * KDIM + kc + s * 8);
    CP_ASYNC16(bufb + 8192 + rh * 64 + swsh,  g_x2h + (j0 + rh) * KDIM + kc + s * 8);
    CP_ASYNC16(bufb + 8192 + r2 * 64 + swsh2, g_x2h + (j0 + r2) * KDIM + kc + s * 8);
}

__device__ __forceinline__ void compute_chunk(uint32_t bufb, int wm, int wn,
                                              int l, float acc[4][4][4]) {
    const int lg = l >> 3, lr = l & 7;
    #pragma unroll
    for (int t = 0; t < 2; t++) {
        uint32_t ah[4][4];
        #pragma unroll
        for (int tm = 0; tm < 4; tm++) {
            const int row  = wm * 64 + tm * 16 + ((lg & 1) << 3) + lr;
            const int slot = 2 * t + (lg >> 1);
            const uint32_t off = row * 64 + ((slot ^ ((row >> 1) & 3)) << 4);
            LDSM_X4(ah[tm][0], ah[tm][1], ah[tm][2], ah[tm][3], bufb + off);
        }
        #pragma unroll
        for (int p = 0; p < 2; p++) {
            const int row  = wn * 32 + p * 16 + ((lg >> 1) << 3) + lr;
            const int slot = 2 * t + (lg & 1);
            const uint32_t off = row * 64 + ((slot ^ ((row >> 1) & 3)) << 4);
            uint32_t bh[4];
            LDSM_X4(bh[0], bh[1], bh[2], bh[3], bufb + 8192 + off);
            #pragma unroll
            for (int tm = 0; tm < 4; tm++) {
                MMA_16816(acc[tm][2 * p],     ah[tm], bh[0], bh[1]);
                MMA_16816(acc[tm][2 * p + 1], ah[tm], bh[2], bh[3]);
            }
        }
    }
}

__global__ __launch_bounds__(256, 2)
void pass1_kernel() {
    __shared__ char smem[4 * CH];
    const uint32_t sb = smem_u32(smem);
    const int tid = threadIdx.x;
    const int l   = tid & 31;
    const int wid = tid >> 5;        // 0..7
    const int wm  = wid >> 2;        // 0..1
    const int wn  = wid & 3;         // 0..3
    const int i0  = blockIdx.y * 128;
    const int j0  = blockIdx.x * 128;

    #pragma unroll
    for (int c = 0; c < 4; c++) {
        load_chunk(sb + c * CH, i0, j0, c * 32, tid);
        CP_COMMIT();
    }

    float acc[4][4][4];
    #pragma unroll
    for (int a = 0; a < 4; a++)
        #pragma unroll
        for (int b = 0; b < 4; b++)
            #pragma unroll
            for (int c = 0; c < 4; c++) acc[a][b][c] = 0.f;

    #pragma unroll
    for (int c = 0; c < 4; c++) {
        switch (c) {
            case 0: asm volatile("cp.async.wait_group 3;" ::: "memory"); break;
            case 1: asm volatile("cp.async.wait_group 2;" ::: "memory"); break;
            case 2: asm volatile("cp.async.wait_group 1;" ::: "memory"); break;
            default: asm volatile("cp.async.wait_group 0;" ::: "memory"); break;
        }
        __syncthreads();
        compute_chunk(sb + c * CH, wm, wn, l, acc);
    }

    // Epilogue: per row, cert = #(m > eps), bord = #(|m| <= eps).
    float na[4], nb[4];
    #pragma unroll
    for (int tn = 0; tn < 4; tn++) {
        const int jb = j0 + wn * 32 + tn * 8 + ((l & 3) << 1);
        na[tn] = __ldg(&g_n2[jb]);
        nb[tn] = __ldg(&g_n2[jb + 1]);
    }

    #pragma unroll
    for (int tm = 0; tm < 4; tm++) {
        const int r0 = i0 + wm * 64 + tm * 16 + (l >> 2);
        const int r1 = r0 + 8;
        const float th0 = __ldg(&g_r[r0]);
        const float th1 = __ldg(&g_r[r1]);
        const float e0  = EPS * __ldg(&g_n1[r0]);
        const float e1  = EPS * __ldg(&g_n1[r1]);
        int p0 = 0, p1 = 0;        // packed (cert<<8 | bord)
        #pragma unroll
        for (int tn = 0; tn < 4; tn++) {
            #pragma unroll
            for (int q = 0; q < 4; q++) {
                const float er  = (q < 2) ? e0 : e1;
                const float th  = (q < 2) ? th0 : th1;
                const float nv  = (q & 1) ? nb[tn] : na[tn];
                const float m   = acc[tm][tn][q] - th * nv;
                const float eps = er * nv;
                int add = (m > eps) ? 256 : ((m >= -eps) ? 1 : 0);
                if (q < 2) p0 += add; else p1 += add;
            }
        }
        p0 += __shfl_xor_sync(0xffffffffu, p0, 1);
        p0 += __shfl_xor_sync(0xffffffffu, p0, 2);
        p1 += __shfl_xor_sync(0xffffffffu, p1, 1);
        p1 += __shfl_xor_sync(0xffffffffu, p1, 2);
        if ((l & 3) == 0) {
            atomicAdd(&g_cb[r0], ((p0 >> 8) << 16) | (p0 & 0xff));
            atomicAdd(&g_cb[r1], ((p1 >> 8) << 16) | (p1 & 0xff));
        }
    }
}

// ---------------------------------------------------------------------------
// Kernel C: decide rows; flag undecidable ones.
// ---------------------------------------------------------------------------
__global__ void flag_kernel() {
    int i = blockIdx.x * blockDim.x + threadIdx.x;
    if (i >= ROWS) return;
    const int cb   = g_cb[i];
    const int cert = cb >> 16;
    const int bord = cb & 0xffff;
    if (cert >= NPER) {
        g_cnt[i] = NPER;               // certainly rank >= NPER: indicator 0
    } else if (cert + bord < NPER) {
        g_cnt[i] = 0;                  // certainly rank < NPER: indicator 1
    } else {
        g_cnt[i] = 0;                  // refined exactly below
        int slot = atomicAdd(&g_nflag, 1);
        g_flag[slot] = i;
    }
}

// ---------------------------------------------------------------------------
// Kernel D: exact fp32 refinement, 8 flagged rows per x2 pass.
// Grid (64 j-slabs, 8 batch-strides), 128 threads. Each CTA stages 8 x1 rows
// in smem, then each thread streams its x2 row ONCE, accumulating 8 dots.
// ---------------------------------------------------------------------------
#define RB 8

__global__ __launch_bounds__(128)
void refine_kernel(const float* __restrict__ x1, const float* __restrict__ x2) {
    __shared__ float rbuf[RB][KDIM];
    __shared__ int   rrow[RB];
    const int tid = threadIdx.x;
    const int j   = blockIdx.x * 128 + tid;
    const float n2j = g_n2[j];
    const int nf = g_nflag;

    for (int b0 = blockIdx.y * RB; b0 < nf; b0 += 8 * RB) {
        const int nb = min(RB, nf - b0);
        __syncthreads();
        // stage up to 8 x1 rows + their row ids
        for (int e = tid; e < nb * KDIM; e += 128) {
            const int er = e >> 7, ec = e & 127;
            rbuf[er][ec] = x1[g_flag[b0 + er] * KDIM + ec];
        }
        if (tid < nb) rrow[tid] = g_flag[b0 + tid];
        __syncthreads();

        float s[RB];
        #pragma unroll
        for (int r = 0; r < RB; r++) s[r] = 0.f;
        const float4* pb = (const float4*)(x2 + j * KDIM);
        #pragma unroll 8
        for (int k = 0; k < 32; k++) {
            const float4 b = pb[k];
            #pragma unroll
            for (int r = 0; r < RB; r++) {
                const float* a = &rbuf[r][k * 4];
                s[r] += a[0] * b.x + a[1] * b.y + a[2] * b.z + a[3] * b.w;
            }
        }
        #pragma unroll
        for (int r = 0; r < RB; r++) {
            if (r >= nb) break;
            const int row = rrow[r];
            int c = (s[r] > __ldg(&g_r[row]) * n2j && j != row) ? 1 : 0;
            #pragma unroll
            for (int o = 16; o > 0; o >>= 1)
                c += __shfl_xor_sync(0xffffffffu, c, o);
            if ((tid & 31) == 0 && c) atomicAdd(&g_cnt[row], c);
        }
    }
}

// ---------------------------------------------------------------------------
// Kernel E: mean of (count < NPER)
// ---------------------------------------------------------------------------
__global__ void finalize_kernel(float* __restrict__ out) {
    __shared__ int sh[1024];
    int t = threadIdx.x;
    int c = 0;
    for (int i = t; i < ROWS; i += 1024) c += (g_cnt[i] < NPER) ? 1 : 0;
    sh[t] = c;
    __syncthreads();
    #pragma unroll
    for (int s = 512; s > 0; s >>= 1) {
        if (t < s) sh[t] += sh[t + s];
        __syncthreads();
    }
    if (t == 0) out[0] = (float)sh[0] / (float)ROWS;
}

// ---------------------------------------------------------------------------
extern "C" void kernel_launch(void* const* d_in, const int* in_sizes, int n_in,
                              void* d_out, int out_size) {
    const float* x1 = (const float*)d_in[0];
    const float* x2 = (const float*)d_in[1];
    float* out = (float*)d_out;
    (void)in_sizes; (void)n_in; (void)out_size;

    prep_kernel<<<ROWS / 8, 256>>>(x1, x2);
    pass1_kernel<<<dim3(64, 64), 256>>>();
    flag_kernel<<<ROWS / 256, 256>>>();
    refine_kernel<<<dim3(64, 8), 128>>>(x1, x2);
    finalize_kernel<<<1, 1024>>>(out);
}